// round 5
// baseline (speedup 1.0000x reference)
#include <cuda_runtime.h>
#include <math.h>
#include <stdint.h>

// NT-Xent loss on GB300: int8 IMMA (mma.sync.m16n8k32.s8) path + symmetry.
// z rows quantized per-row to int8 (scale folds in the L2 normalization).
// S = z z^T computed only on upper-triangle 128x128 block pairs; each
// off-diagonal tile contributes row sums AND column (=transposed row) sums.
// exp via ex2.approx with scales folded: exp(s_r*s_c*dot*10).

#define NROWS 8192
#define NC    512
#define BHALF 4096
#define NB    (NROWS / 128)         // 64
#define NPAIRS (NB * (NB + 1) / 2)  // 2080

#define BM 128
#define BN 128
#define BK 128                       // int8 k-bytes per stage
#define KITERS (NC / BK)             // 4
#define NSTAGE 3
#define STAGE_BYTES (2 * BM * BK)    // A + B = 32768
#define SMEM_TOTAL (NSTAGE * STAGE_BYTES)  // 98304

__device__ __align__(1024) int8_t g_zq[(size_t)NROWS * NC];
__device__ float g_scale[NROWS];
__device__ float g_pos[BHALF];
__device__ float g_rs[(size_t)NROWS * NB];
__device__ float g_part[NB];

__device__ __forceinline__ uint32_t smem_u32(const void* p) {
    uint32_t a;
    asm("{ .reg .u64 t; cvta.to.shared.u64 t, %1; cvt.u32.u64 %0, t; }"
        : "=r"(a) : "l"(p));
    return a;
}
__device__ __forceinline__ float ex2f(float x) {
    float y;
    asm("ex2.approx.ftz.f32 %0, %1;" : "=f"(y) : "f"(x));
    return y;
}

#define CP_ASYNC16(dst, src) \
    asm volatile("cp.async.cg.shared.global [%0], [%1], 16;" :: "r"(dst), "l"(src) : "memory")
#define CP_COMMIT() asm volatile("cp.async.commit_group;" ::: "memory")

#define LDSM_X4(r0, r1, r2, r3, addr)                                          \
    asm volatile("ldmatrix.sync.aligned.m8n8.x4.shared.b16 {%0,%1,%2,%3}, [%4];" \
                 : "=r"(r0), "=r"(r1), "=r"(r2), "=r"(r3) : "r"(addr))

#define IMMA16832(c, a0, a1, a2, a3, b0, b1)                                   \
    asm volatile("mma.sync.aligned.m16n8k32.row.col.s32.s8.s8.s32 "            \
                 "{%0,%1,%2,%3},{%4,%5,%6,%7},{%8,%9},{%0,%1,%2,%3};"          \
                 : "+r"((c)[0]), "+r"((c)[1]), "+r"((c)[2]), "+r"((c)[3])      \
                 : "r"(a0), "r"(a1), "r"(a2), "r"(a3), "r"(b0), "r"(b1))

// 10 / ln(2)
#define TEN_LOG2E 14.4269504088896341f

// ---------------------------------------------------------------------------
// Kernel 1: per-row symmetric int8 quantization; scale absorbs L2 norm.
// q_i = rn(127 * z_i / max|z_row|),  s_r = max|z_row| / (127 * max(||z||,eps))
// so  s_r * q_i ~= z_i / ||z||.
// ---------------------------------------------------------------------------
__global__ void quant_kernel(const float* __restrict__ z1,
                             const float* __restrict__ z2) {
    int r = blockIdx.x;
    const float* row = (r < BHALF) ? (z1 + (size_t)r * NC)
                                   : (z2 + (size_t)(r - BHALF) * NC);
    int t = threadIdx.x;  // 128 threads, float4 each
    float4 v = ((const float4*)row)[t];
    float ss = v.x * v.x + v.y * v.y + v.z * v.z + v.w * v.w;
    float ma = fmaxf(fmaxf(fabsf(v.x), fabsf(v.y)), fmaxf(fabsf(v.z), fabsf(v.w)));
#pragma unroll
    for (int o = 16; o; o >>= 1) {
        ss += __shfl_xor_sync(0xFFFFFFFFu, ss, o);
        ma = fmaxf(ma, __shfl_xor_sync(0xFFFFFFFFu, ma, o));
    }
    __shared__ float wss[4], wma[4];
    if ((t & 31) == 0) { wss[t >> 5] = ss; wma[t >> 5] = ma; }
    __syncthreads();
    ss = wss[0] + wss[1] + wss[2] + wss[3];
    ma = fmaxf(fmaxf(wma[0], wma[1]), fmaxf(wma[2], wma[3]));
    float inv = 1.0f / fmaxf(sqrtf(ss), 1e-12f);
    float qs = 127.0f / ma;
    char4 q;
    q.x = (char)__float2int_rn(v.x * qs);
    q.y = (char)__float2int_rn(v.y * qs);
    q.z = (char)__float2int_rn(v.z * qs);
    q.w = (char)__float2int_rn(v.w * qs);
    ((char4*)g_zq)[(size_t)r * (NC / 4) + t] = q;
    if (t == 0) g_scale[r] = ma * inv * (1.0f / 127.0f);
}

// ---------------------------------------------------------------------------
// Kernel 2: fused int8 GEMM + exp + row/col sums + positive capture.
// 256 threads = 8 warps in 2(M) x 4(N); warp tile 64x32 via m16n8k32.
// ---------------------------------------------------------------------------
__global__ __launch_bounds__(256, 2) void gemm_kernel() {
    extern __shared__ __align__(1024) char smem[];
    const int tid = threadIdx.x;
    const int lane = tid & 31;
    const int w = tid >> 5;
    const int wm = w >> 2;
    const int wn = w & 3;

    // linear block id -> upper-triangle pair (bm <= bn)
    int rem = blockIdx.x;
    int bm = 0;
#pragma unroll 1
    while (rem >= (NB - bm)) { rem -= (NB - bm); bm++; }
    const int bn = bm + rem;
    const int r0 = bm * BM;
    const int c0 = bn * BN;
    const uint32_t sbase = smem_u32(smem);

    // ---- cp.async: 256 threads -> 256 tile rows (128 A + 128 B), 128B each --
    const int half = tid >> 7;
    const int lrow = tid & 127;
    const char* grow = (const char*)g_zq +
        ((size_t)((half ? c0 : r0) + lrow)) * NC;
    const uint32_t sdst = sbase + (uint32_t)half * (BM * BK) +
                          (uint32_t)lrow * 128u;
    const uint32_t xr = ((uint32_t)lrow & 7u) << 4;

#define ISSUE_STAGE(s_)                                                        \
    do {                                                                       \
        const char* g_ = grow + (s_) * BK;                                     \
        uint32_t d_ = sdst + (uint32_t)((s_) % NSTAGE) * STAGE_BYTES;          \
        _Pragma("unroll")                                                      \
        for (int c_ = 0; c_ < 8; c_++)                                         \
            CP_ASYNC16(d_ + (((uint32_t)c_ * 16u) ^ xr), g_ + c_ * 16);        \
        CP_COMMIT();                                                           \
    } while (0)

    ISSUE_STAGE(0);
    ISSUE_STAGE(1);

    // ---- ldmatrix address precompute (16B chunks; identical to bf16 case) --
    uint32_t addrA[4], xA[4];
    const uint32_t chunkA = ((uint32_t)(lane >> 4)) * 16u;
#pragma unroll
    for (int mi = 0; mi < 4; mi++) {
        int rA = wm * 64 + mi * 16 + (lane & 15);
        addrA[mi] = sbase + (uint32_t)rA * 128u;
        xA[mi] = ((uint32_t)rA & 7u) << 4;
    }
    uint32_t addrB[2], xB[2];
    const uint32_t chunkB = ((uint32_t)((lane >> 3) & 1)) * 16u;
#pragma unroll
    for (int np = 0; np < 2; np++) {
        int rB = wn * 32 + np * 16 + ((lane >> 4) & 1) * 8 + (lane & 7);
        addrB[np] = sbase + (uint32_t)(BM * BK) + (uint32_t)rB * 128u;
        xB[np] = ((uint32_t)rB & 7u) << 4;
    }

    int acc[4][4][4];
#pragma unroll
    for (int mi = 0; mi < 4; mi++)
#pragma unroll
        for (int ni = 0; ni < 4; ni++)
#pragma unroll
            for (int e = 0; e < 4; e++) acc[mi][ni][e] = 0;

    // ---- mainloop: 4 k-iters of 128 bytes, 4 k32 steps each ----
#pragma unroll 1
    for (int i = 0; i < KITERS; i++) {
        if (i < KITERS - 1)
            asm volatile("cp.async.wait_group 1;" ::: "memory");
        else
            asm volatile("cp.async.wait_group 0;" ::: "memory");
        __syncthreads();
        if (i + 2 < KITERS) ISSUE_STAGE(i + 2);

        const uint32_t sb = (uint32_t)(i % NSTAGE) * STAGE_BYTES;
#pragma unroll
        for (int kk = 0; kk < 4; kk++) {
            const uint32_t kkb = (uint32_t)kk * 32u;
            uint32_t a[4][4], b[2][4];
#pragma unroll
            for (int mi = 0; mi < 4; mi++)
                LDSM_X4(a[mi][0], a[mi][1], a[mi][2], a[mi][3],
                        addrA[mi] + sb + ((kkb | chunkA) ^ xA[mi]));
#pragma unroll
            for (int np = 0; np < 2; np++)
                LDSM_X4(b[np][0], b[np][1], b[np][2], b[np][3],
                        addrB[np] + sb + ((kkb | chunkB) ^ xB[np]));
#pragma unroll
            for (int mi = 0; mi < 4; mi++)
#pragma unroll
                for (int ni = 0; ni < 4; ni++)
                    IMMA16832(acc[mi][ni],
                              a[mi][0], a[mi][1], a[mi][2], a[mi][3],
                              b[ni >> 1][(ni & 1) * 2],
                              b[ni >> 1][(ni & 1) * 2 + 1]);
        }
    }

    // ---- epilogue: dequant+exp, positive capture, row/col partials ----
    float srow14[4][2], scolv[4][2];
#pragma unroll
    for (int mi = 0; mi < 4; mi++)
#pragma unroll
        for (int h = 0; h < 2; h++)
            srow14[mi][h] =
                g_scale[r0 + wm * 64 + mi * 16 + h * 8 + (lane >> 2)] * TEN_LOG2E;
#pragma unroll
    for (int ni = 0; ni < 4; ni++)
#pragma unroll
        for (int b = 0; b < 2; b++)
            scolv[ni][b] = g_scale[c0 + wn * 32 + ni * 8 + (lane & 3) * 2 + b];

    float vr[4][2];   // row partials
    float cv[4][2];   // col partials
#pragma unroll
    for (int i = 0; i < 4; i++) {
        vr[i][0] = vr[i][1] = 0.f;
        cv[i][0] = cv[i][1] = 0.f;
    }

#pragma unroll
    for (int mi = 0; mi < 4; mi++) {
#pragma unroll
        for (int ni = 0; ni < 4; ni++) {
#pragma unroll
            for (int e = 0; e < 4; e++) {
                float fi = __int2float_rn(acc[mi][ni][e]);
                float v = ex2f(fi * (srow14[mi][e >> 1] * scolv[ni][e & 1]));
                vr[mi][e >> 1] += v;
                cv[ni][e & 1] += v;
                int rowg = r0 + wm * 64 + mi * 16 + (e >> 1) * 8 + (lane >> 2);
                int col = c0 + wn * 32 + ni * 8 + (lane & 3) * 2 + (e & 1);
                if (col == rowg + BHALF) g_pos[rowg] = v;  // only fires r<B
            }
        }
    }
    // rows: reduce across lanes sharing a row (lane&3)
#pragma unroll
    for (int mi = 0; mi < 4; mi++)
#pragma unroll
        for (int h = 0; h < 2; h++) {
            float v = vr[mi][h];
            v += __shfl_xor_sync(0xFFFFFFFFu, v, 1);
            v += __shfl_xor_sync(0xFFFFFFFFu, v, 2);
            vr[mi][h] = v;
        }
    // cols: reduce across lane-groups sharing a col (lane>>2)
#pragma unroll
    for (int ni = 0; ni < 4; ni++)
#pragma unroll
        for (int b = 0; b < 2; b++) {
            float v = cv[ni][b];
            v += __shfl_xor_sync(0xFFFFFFFFu, v, 4);
            v += __shfl_xor_sync(0xFFFFFFFFu, v, 8);
            v += __shfl_xor_sync(0xFFFFFFFFu, v, 16);
            cv[ni][b] = v;
        }

    __syncthreads();               // stage buffers dead; reuse smem
    float* redr = (float*)smem;          // [4 wn][128 rows]
    float* redc = (float*)smem + 512;    // [2 wm][128 cols]
    if ((lane & 3) == 0) {
#pragma unroll
        for (int mi = 0; mi < 4; mi++)
#pragma unroll
            for (int h = 0; h < 2; h++)
                redr[wn * 128 + wm * 64 + mi * 16 + h * 8 + (lane >> 2)] = vr[mi][h];
    }
    if (lane < 4) {
#pragma unroll
        for (int ni = 0; ni < 4; ni++)
#pragma unroll
            for (int b = 0; b < 2; b++)
                redc[wm * 128 + wn * 32 + ni * 8 + lane * 2 + b] = cv[ni][b];
    }
    __syncthreads();
    if (tid < 128) {
        float t = redr[tid] + redr[128 + tid] + redr[256 + tid] + redr[384 + tid];
        g_rs[((size_t)(r0 + tid)) * NB + bn] = t;
    } else if (bm != bn) {
        int t2 = tid - 128;
        float t = redc[t2] + redc[128 + t2];
        g_rs[((size_t)(c0 + t2)) * NB + bm] = t;
    }
}

// ---------------------------------------------------------------------------
// Kernel 3a: per-128-row partial loss sums (64 blocks, deterministic)
// ---------------------------------------------------------------------------
__global__ void loss_part_kernel() {
    int r = blockIdx.x * 128 + threadIdx.x;
    const float4* p4 = (const float4*)&g_rs[(size_t)r * NB];
    float tot = 0.f;
#pragma unroll
    for (int i = 0; i < NB / 4; i++) {
        float4 q = p4[i];
        tot += (q.x + q.y) + (q.z + q.w);
    }
    float p = g_pos[r & (BHALF - 1)];
    float s = logf(tot - p) - logf(p);
#pragma unroll
    for (int o = 16; o; o >>= 1) s += __shfl_xor_sync(0xFFFFFFFFu, s, o);
    __shared__ float ws[4];
    if ((threadIdx.x & 31) == 0) ws[threadIdx.x >> 5] = s;
    __syncthreads();
    if (threadIdx.x == 0)
        g_part[blockIdx.x] = ws[0] + ws[1] + ws[2] + ws[3];
}

// ---------------------------------------------------------------------------
// Kernel 3b: final scalar
// ---------------------------------------------------------------------------
__global__ void loss_final_kernel(float* __restrict__ out) {
    float s = g_part[threadIdx.x] + g_part[threadIdx.x + 32];
#pragma unroll
    for (int o = 16; o; o >>= 1) s += __shfl_xor_sync(0xFFFFFFFFu, s, o);
    if (threadIdx.x == 0)
        out[0] = s / ((float)NROWS * (float)BHALF);
}

extern "C" void kernel_launch(void* const* d_in, const int* in_sizes, int n_in,
                              void* d_out, int out_size) {
    const float* z1 = (const float*)d_in[0];
    const float* z2 = (const float*)d_in[1];
    (void)in_sizes; (void)n_in; (void)out_size;

    cudaFuncSetAttribute(gemm_kernel, cudaFuncAttributeMaxDynamicSharedMemorySize,
                         SMEM_TOTAL);

    quant_kernel<<<NROWS, 128>>>(z1, z2);
    gemm_kernel<<<NPAIRS, 256, SMEM_TOTAL>>>();
    loss_part_kernel<<<NB, 128>>>();
    loss_final_kernel<<<1, 32>>>((float*)d_out);
}

// round 6
// speedup vs baseline: 1.1124x; 1.1124x over previous
#include <cuda_runtime.h>
#include <cuda_fp16.h>
#include <math.h>
#include <stdint.h>

// NT-Xent loss on GB300, HMMA fp16-accumulate path + symmetry.
// S = z z^T on upper-triangle 128x128 block pairs only (2080 of 4096).
// mma.sync.m16n8k16.f16 (f16 accumulators) to probe the legacy pipe's
// double-rate f16-acc mode; promote to fp32 in the epilogue.

#define NROWS 8192
#define NC    512
#define BHALF 4096
#define NB    (NROWS / 128)         // 64
#define NPAIRS (NB * (NB + 1) / 2)  // 2080

#define BM 128
#define BN 128
#define BK 64
#define KITERS (NC / BK)        // 8
#define NSTAGE 3
#define STAGE_BYTES (2 * BM * BK * 2)   // A + B = 32768
#define SMEM_TOTAL (NSTAGE * STAGE_BYTES)  // 98304

__device__ __align__(1024) __half g_zn[(size_t)NROWS * NC];
__device__ float g_pos[BHALF];
__device__ float g_rs[(size_t)NROWS * NB];

__device__ __forceinline__ uint32_t smem_u32(const void* p) {
    uint32_t a;
    asm("{ .reg .u64 t; cvta.to.shared.u64 t, %1; cvt.u32.u64 %0, t; }"
        : "=r"(a) : "l"(p));
    return a;
}

#define CP_ASYNC16(dst, src) \
    asm volatile("cp.async.cg.shared.global [%0], [%1], 16;" :: "r"(dst), "l"(src) : "memory")
#define CP_COMMIT() asm volatile("cp.async.commit_group;" ::: "memory")

#define LDSM_X4(r0, r1, r2, r3, addr)                                          \
    asm volatile("ldmatrix.sync.aligned.m8n8.x4.shared.b16 {%0,%1,%2,%3}, [%4];" \
                 : "=r"(r0), "=r"(r1), "=r"(r2), "=r"(r3) : "r"(addr))

// f16-accumulate HMMA: D(f16x2 x2) = A(f16) * B(f16) + D
#define MMAF16(c, a0, a1, a2, a3, b0, b1)                                      \
    asm volatile("mma.sync.aligned.m16n8k16.row.col.f16.f16.f16.f16 "          \
                 "{%0,%1},{%2,%3,%4,%5},{%6,%7},{%0,%1};"                      \
                 : "+r"((c)[0]), "+r"((c)[1])                                  \
                 : "r"(a0), "r"(a1), "r"(a2), "r"(a3), "r"(b0), "r"(b1))

// ---------------------------------------------------------------------------
// Kernel 1: L2-normalize rows, emit fp16 z
// ---------------------------------------------------------------------------
__global__ void normalize_kernel(const float* __restrict__ z1,
                                 const float* __restrict__ z2) {
    int r = blockIdx.x;
    const float* row = (r < BHALF) ? (z1 + (size_t)r * NC)
                                   : (z2 + (size_t)(r - BHALF) * NC);
    int t = threadIdx.x;
    float4 v = ((const float4*)row)[t];
    float s = v.x * v.x + v.y * v.y + v.z * v.z + v.w * v.w;
#pragma unroll
    for (int o = 16; o; o >>= 1) s += __shfl_xor_sync(0xFFFFFFFFu, s, o);
    __shared__ float ws[4];
    if ((t & 31) == 0) ws[t >> 5] = s;
    __syncthreads();
    s = ws[0] + ws[1] + ws[2] + ws[3];
    float inv = 1.0f / fmaxf(sqrtf(s), 1e-12f);
    __half2 lo = __floats2half2_rn(v.x * inv, v.y * inv);
    __half2 hi = __floats2half2_rn(v.z * inv, v.w * inv);
    __half2* dst = (__half2*)g_zn + (size_t)r * (NC / 2) + t * 2;
    dst[0] = lo;
    dst[1] = hi;
}

// ---------------------------------------------------------------------------
// Kernel 2: fused GEMM + exp + row/col sums + positive capture (upper tri).
// 256 threads = 8 warps in 2(M) x 4(N); warp tile 64x32 via m16n8k16.
// ---------------------------------------------------------------------------
__global__ __launch_bounds__(256, 2) void gemm_kernel() {
    extern __shared__ __align__(1024) char smem[];
    const int tid = threadIdx.x;
    const int lane = tid & 31;
    const int w = tid >> 5;
    const int wm = w >> 2;       // 0..1
    const int wn = w & 3;        // 0..3

    // map linear block id -> upper-triangle pair (bm <= bn)
    int rem = blockIdx.x;
    int bm = 0;
#pragma unroll 1
    while (rem >= (NB - bm)) { rem -= (NB - bm); bm++; }
    const int bn = bm + rem;
    const int r0 = bm * BM;
    const int c0 = bn * BN;
    const uint32_t sbase = smem_u32(smem);

    // ---- cp.async mapping: 256 threads -> 256 tile rows (128 A + 128 B) ----
    const int half = tid >> 7;          // 0 = A (rows), 1 = B (cols)
    const int lrow = tid & 127;
    const char* grow = (const char*)g_zn +
        ((size_t)((half ? c0 : r0) + lrow)) * (NC * 2);
    const uint32_t sdst = sbase + (uint32_t)half * (BM * BK * 2) +
                          (uint32_t)lrow * 128u;
    const uint32_t xr = ((uint32_t)lrow & 7u) << 4;

#define ISSUE_STAGE(s_)                                                        \
    do {                                                                       \
        const char* g_ = grow + (s_) * (BK * 2);                               \
        uint32_t d_ = sdst + (uint32_t)((s_) % NSTAGE) * STAGE_BYTES;          \
        _Pragma("unroll")                                                      \
        for (int c_ = 0; c_ < 8; c_++)                                         \
            CP_ASYNC16(d_ + (((uint32_t)c_ * 16u) ^ xr), g_ + c_ * 16);        \
        CP_COMMIT();                                                           \
    } while (0)

    ISSUE_STAGE(0);
    ISSUE_STAGE(1);

    // ---- ldmatrix address precompute ----
    uint32_t addrA[4], xA[4];
    const uint32_t chunkA = ((uint32_t)(lane >> 4)) * 16u;
#pragma unroll
    for (int mi = 0; mi < 4; mi++) {
        int rA = wm * 64 + mi * 16 + (lane & 15);
        addrA[mi] = sbase + (uint32_t)rA * 128u;
        xA[mi] = ((uint32_t)rA & 7u) << 4;
    }
    uint32_t addrB[2], xB[2];
    const uint32_t chunkB = ((uint32_t)((lane >> 3) & 1)) * 16u;
#pragma unroll
    for (int np = 0; np < 2; np++) {
        int rB = wn * 32 + np * 16 + ((lane >> 4) & 1) * 8 + (lane & 7);
        addrB[np] = sbase + (uint32_t)(BM * BK * 2) + (uint32_t)rB * 128u;
        xB[np] = ((uint32_t)rB & 7u) << 4;
    }

    uint32_t acc[4][4][2];   // f16x2 accumulators
#pragma unroll
    for (int mi = 0; mi < 4; mi++)
#pragma unroll
        for (int ni = 0; ni < 4; ni++) {
            acc[mi][ni][0] = 0u;
            acc[mi][ni][1] = 0u;
        }

    // ---- mainloop ----
#pragma unroll 1
    for (int i = 0; i < KITERS; i++) {
        if (i < KITERS - 1)
            asm volatile("cp.async.wait_group 1;" ::: "memory");
        else
            asm volatile("cp.async.wait_group 0;" ::: "memory");
        __syncthreads();
        if (i + 2 < KITERS) ISSUE_STAGE(i + 2);

        const uint32_t sb = (uint32_t)(i % NSTAGE) * STAGE_BYTES;
#pragma unroll
        for (int kk = 0; kk < 4; kk++) {
            const uint32_t kkb = (uint32_t)kk * 32u;
            uint32_t a[4][4], b[2][4];
#pragma unroll
            for (int mi = 0; mi < 4; mi++)
                LDSM_X4(a[mi][0], a[mi][1], a[mi][2], a[mi][3],
                        addrA[mi] + sb + ((kkb | chunkA) ^ xA[mi]));
#pragma unroll
            for (int np = 0; np < 2; np++)
                LDSM_X4(b[np][0], b[np][1], b[np][2], b[np][3],
                        addrB[np] + sb + ((kkb | chunkB) ^ xB[np]));
#pragma unroll
            for (int mi = 0; mi < 4; mi++)
#pragma unroll
                for (int ni = 0; ni < 4; ni++)
                    MMAF16(acc[mi][ni],
                           a[mi][0], a[mi][1], a[mi][2], a[mi][3],
                           b[ni >> 1][(ni & 1) * 2],
                           b[ni >> 1][(ni & 1) * 2 + 1]);
        }
    }

    // ---- epilogue: promote f16->f32, exp, positive capture, row/col sums --
    float vr[4][2];   // row partials: [mi][half-row h]
    float cv[4][2];   // col partials: [ni][col parity b]
#pragma unroll
    for (int i = 0; i < 4; i++) {
        vr[i][0] = vr[i][1] = 0.f;
        cv[i][0] = cv[i][1] = 0.f;
    }

#pragma unroll
    for (int mi = 0; mi < 4; mi++) {
#pragma unroll
        for (int ni = 0; ni < 4; ni++) {
#pragma unroll
            for (int h = 0; h < 2; h++) {
                float2 f = __half22float2(*(__half2*)&acc[mi][ni][h]);
                int rowg = r0 + wm * 64 + mi * 16 + h * 8 + (lane >> 2);
                int colb = c0 + wn * 32 + ni * 8 + (lane & 3) * 2;
                float v0 = __expf(f.x * 10.0f);
                float v1 = __expf(f.y * 10.0f);
                vr[mi][h] += v0 + v1;
                cv[ni][0] += v0;
                cv[ni][1] += v1;
                if (colb == rowg + BHALF) g_pos[rowg] = v0;      // b = 0
                if (colb + 1 == rowg + BHALF) g_pos[rowg] = v1;  // b = 1
            }
        }
    }
    // rows: reduce across the 4 lanes sharing each row (lane&3 varies)
#pragma unroll
    for (int mi = 0; mi < 4; mi++)
#pragma unroll
        for (int h = 0; h < 2; h++) {
            float v = vr[mi][h];
            v += __shfl_xor_sync(0xFFFFFFFFu, v, 1);
            v += __shfl_xor_sync(0xFFFFFFFFu, v, 2);
            vr[mi][h] = v;
        }
    // cols: reduce across the 8 lane-groups sharing each col (lane>>2 varies)
#pragma unroll
    for (int ni = 0; ni < 4; ni++)
#pragma unroll
        for (int b = 0; b < 2; b++) {
            float v = cv[ni][b];
            v += __shfl_xor_sync(0xFFFFFFFFu, v, 4);
            v += __shfl_xor_sync(0xFFFFFFFFu, v, 8);
            v += __shfl_xor_sync(0xFFFFFFFFu, v, 16);
            cv[ni][b] = v;
        }

    __syncthreads();               // stage buffers dead; reuse smem
    float* redr = (float*)smem;          // [4 wn][128 rows]
    float* redc = (float*)smem + 512;    // [2 wm][128 cols]
    if ((lane & 3) == 0) {
#pragma unroll
        for (int mi = 0; mi < 4; mi++)
#pragma unroll
            for (int h = 0; h < 2; h++)
                redr[wn * 128 + wm * 64 + mi * 16 + h * 8 + (lane >> 2)] = vr[mi][h];
    }
    if (lane < 4) {
#pragma unroll
        for (int ni = 0; ni < 4; ni++)
#pragma unroll
            for (int b = 0; b < 2; b++)
                redc[wm * 128 + wn * 32 + ni * 8 + lane * 2 + b] = cv[ni][b];
    }
    __syncthreads();
    if (tid < 128) {
        float t = redr[tid] + redr[128 + tid] + redr[256 + tid] + redr[384 + tid];
        g_rs[((size_t)(r0 + tid)) * NB + bn] = t;
    } else if (bm != bn) {
        int t2 = tid - 128;
        float t = redc[t2] + redc[128 + t2];
        g_rs[((size_t)(c0 + t2)) * NB + bm] = t;
    }
}

// ---------------------------------------------------------------------------
// Kernel 3: loss = sum_r [log(rowsum_r - pos_r) - log(pos_r)] / (N*B)
// ---------------------------------------------------------------------------
__global__ void loss_kernel(float* __restrict__ out) {
    __shared__ float ws[8];
    float s = 0.f;
    for (int r = threadIdx.x; r < NROWS; r += blockDim.x) {
        const float4* p4 = (const float4*)&g_rs[(size_t)r * NB];
        float tot = 0.f;
#pragma unroll
        for (int i = 0; i < NB / 4; i++) {
            float4 q = p4[i];
            tot += (q.x + q.y) + (q.z + q.w);
        }
        float p = g_pos[r & (BHALF - 1)];
        s += logf(tot - p) - logf(p);
    }
#pragma unroll
    for (int o = 16; o; o >>= 1) s += __shfl_xor_sync(0xFFFFFFFFu, s, o);
    if ((threadIdx.x & 31) == 0) ws[threadIdx.x >> 5] = s;
    __syncthreads();
    if (threadIdx.x < 8) {
        float v = ws[threadIdx.x];
#pragma unroll
        for (int o = 4; o; o >>= 1) v += __shfl_xor_sync(0xFFu, v, o);
        if (threadIdx.x == 0)
            out[0] = v / ((float)NROWS * (float)BHALF);
    }
}

extern "C" void kernel_launch(void* const* d_in, const int* in_sizes, int n_in,
                              void* d_out, int out_size) {
    const float* z1 = (const float*)d_in[0];
    const float* z2 = (const float*)d_in[1];
    (void)in_sizes; (void)n_in; (void)out_size;

    cudaFuncSetAttribute(gemm_kernel, cudaFuncAttributeMaxDynamicSharedMemorySize,
                         SMEM_TOTAL);

    normalize_kernel<<<NROWS, 128>>>(z1, z2);
    gemm_kernel<<<NPAIRS, 256, SMEM_TOTAL>>>();
    loss_kernel<<<1, 256>>>((float*)d_out);
}